// round 17
// baseline (speedup 1.0000x reference)
#include <cuda_runtime.h>
#include <mma.h>
#include <math.h>
#include <stdint.h>

using namespace nvcuda;

#define M0 16
#define M1 8
#define Q0 8
#define Q1 4
#define O0 16
#define O1 8
#define HID 32
#define EB 16
#define TPK 320
#define TPV 640
#define NODE_DIM 40
#define OUT_DIM 40
#define N_MAX 20000
#define E_MAX 250000

__device__ float g_qts[N_MAX * Q0];
__device__ float g_qtv[N_MAX * Q1 * 3];
__device__ float g_ex[E_MAX];
__device__ float g_z[N_MAX];
// tf32 hi/lo images of W2 ([h][c] row-major, i.e. K x N)
__device__ __align__(16) float g_wk_hi[HID * TPK], g_wk_lo[HID * TPK];
__device__ __align__(16) float g_wv_hi[HID * TPV], g_wv_lo[HID * TPV];

#define INV_SQRT3 0.57735026918962576f
#define INV_SQRT2 0.70710678118654752f
#define INV_SQRT24 0.20412414523193151f
#define INV_SQRT32 0.17677669529663687f
#define INV_SQRT8 0.35355339059327373f
#define CS_FOLD 0.022821773229381923f     // 1/sqrt(24*80)
#define CV_FOLD 0.011410886614690962f     // 1/sqrt(32*3*80)

// ---------------------------------------------------------------------------
// q_kernel: per-node q-tilde (wdot + norms folded), zero z and out.
// ---------------------------------------------------------------------------
__global__ void q_kernel(const float* __restrict__ node_ft,
                         const float* __restrict__ wqs, const float* __restrict__ wqv,
                         const float* __restrict__ wds, const float* __restrict__ wdv,
                         float* __restrict__ out, int N)
{
    int n = blockIdx.x * blockDim.x + threadIdx.x;
    if (n >= N) return;
    const float* x = node_ft + (size_t)n * NODE_DIM;
    float xs[M0], xv[M1][3];
#pragma unroll
    for (int i = 0; i < M0; i++) xs[i] = x[i];
#pragma unroll
    for (int i = 0; i < M1; i++)
#pragma unroll
        for (int c = 0; c < 3; c++) xv[i][c] = x[M0 + i * 3 + c];
    float qs[Q0];
#pragma unroll
    for (int o = 0; o < Q0; o++) {
        float t = 0.f;
#pragma unroll
        for (int i = 0; i < M0; i++) t += xs[i] * wqs[i * Q0 + o];
        qs[o] = t * 0.25f;
    }
    float qv[Q1][3];
#pragma unroll
    for (int o = 0; o < Q1; o++)
#pragma unroll
        for (int c = 0; c < 3; c++) {
            float t = 0.f;
#pragma unroll
            for (int i = 0; i < M1; i++) t += xv[i][c] * wqv[i * Q1 + o];
            qv[o][c] = t * INV_SQRT8;
        }
#pragma unroll
    for (int j = 0; j < Q0; j++) {
        float t = 0.f;
#pragma unroll
        for (int i = 0; i < Q0; i++) t += qs[i] * wds[i * Q0 + j];
        g_qts[n * Q0 + j] = t * CS_FOLD;
    }
#pragma unroll
    for (int j = 0; j < Q1; j++)
#pragma unroll
        for (int c = 0; c < 3; c++) {
            float t = 0.f;
#pragma unroll
            for (int i = 0; i < Q1; i++) t += qv[i][c] * wdv[i * Q1 + j];
            g_qtv[n * 12 + j * 3 + c] = t * CV_FOLD;
        }
    g_z[n] = 0.f;
#pragma unroll
    for (int k = 0; k < OUT_DIM; k++) out[(size_t)n * OUT_DIM + k] = 0.f;
}

// ---------------------------------------------------------------------------
// prep: tf32 hi/lo split of both W2 matrices (layout unchanged: [h][c]).
// ---------------------------------------------------------------------------
__global__ void prep_kernel(const float* __restrict__ wk, const float* __restrict__ wv)
{
    int tot = HID * (TPK + TPV);
    for (int idx = blockIdx.x * blockDim.x + threadIdx.x; idx < tot;
         idx += gridDim.x * blockDim.x) {
        if (idx < HID * TPK) {
            float v = wk[idx];
            float hi = wmma::__float_to_tf32(v);
            g_wk_hi[idx] = hi;
            g_wk_lo[idx] = wmma::__float_to_tf32(v - hi);
        } else {
            int j = idx - HID * TPK;
            float v = wv[j];
            float hi = wmma::__float_to_tf32(v);
            g_wv_hi[j] = hi;
            g_wv_lo[j] = wmma::__float_to_tf32(v - hi);
        }
    }
}

// one weff column applied to the CG paths (runtime col, uniform branches)
template<int PASS>
__device__ __forceinline__ void apply1(int c, float f,
    const float* xs, const float* pvv, const float* xvf, const float* cr,
    float sh0, float shx, float shy, float shz, float* sa, float* va)
{
    if (PASS == 1) {
        if (c < 128)      { int i = c >> 3, o = c & 7; sa[o] = fmaf(f * sh0, xs[i], sa[o]); }
        else if (c < 192) { int r = c - 128, i = r >> 3, o = r & 7; sa[o] = fmaf(f, pvv[i], sa[o]); }
        else if (c < 256) { int r = c - 192, i = r >> 2, o = r & 3; float t = f * xs[i];
            va[o*3+0] = fmaf(t, shx, va[o*3+0]); va[o*3+1] = fmaf(t, shy, va[o*3+1]); va[o*3+2] = fmaf(t, shz, va[o*3+2]); }
        else if (c < 288) { int r = c - 256, i = r >> 2, o = r & 3; float t = f * sh0;
            va[o*3+0] = fmaf(t, xvf[i*3+0], va[o*3+0]); va[o*3+1] = fmaf(t, xvf[i*3+1], va[o*3+1]); va[o*3+2] = fmaf(t, xvf[i*3+2], va[o*3+2]); }
        else              { int r = c - 288, i = r >> 2, o = r & 3;
            va[o*3+0] = fmaf(f, cr[i*3+0], va[o*3+0]); va[o*3+1] = fmaf(f, cr[i*3+1], va[o*3+1]); va[o*3+2] = fmaf(f, cr[i*3+2], va[o*3+2]); }
    } else {
        if (c < 256)      { int i = c >> 4, o = c & 15; sa[o] = fmaf(f * sh0, xs[i], sa[o]); }
        else if (c < 384) { int r = c - 256, i = r >> 4, o = r & 15; sa[o] = fmaf(f, pvv[i], sa[o]); }
        else if (c < 512) { int r = c - 384, i = r >> 3, o = r & 7; float t = f * xs[i];
            va[o*3+0] = fmaf(t, shx, va[o*3+0]); va[o*3+1] = fmaf(t, shy, va[o*3+1]); va[o*3+2] = fmaf(t, shz, va[o*3+2]); }
        else if (c < 576) { int r = c - 512, i = r >> 3, o = r & 7; float t = f * sh0;
            va[o*3+0] = fmaf(t, xvf[i*3+0], va[o*3+0]); va[o*3+1] = fmaf(t, xvf[i*3+1], va[o*3+1]); va[o*3+2] = fmaf(t, xvf[i*3+2], va[o*3+2]); }
        else              { int r = c - 576, i = r >> 3, o = r & 7;
            va[o*3+0] = fmaf(f, cr[i*3+0], va[o*3+0]); va[o*3+1] = fmaf(f, cr[i*3+1], va[o*3+1]); va[o*3+2] = fmaf(f, cr[i*3+2], va[o*3+2]); }
    }
}

// smem (floats): sW1 512 | Hhi 128*36 | Hlo 128*36 | Bh 32*68 | Bl 32*68 | Cb 128*68
#define SMF (512 + 2 * 128 * 36 + 2 * 32 * 68 + 128 * 68)

template<int PASS>
__global__ void __launch_bounds__(128, 2) tf_pass(
    const float* __restrict__ node_ft, const int* __restrict__ eidx,
    const float* __restrict__ edge_sh, const float* __restrict__ edge_sc,
    const float* __restrict__ W1g, float* __restrict__ out, int E)
{
    constexpr int TP = (PASS == 1) ? TPK : TPV;
    constexpr int NCH = TP / 64;
    extern __shared__ float sm[];
    float* sW1 = sm;
    float* Hhi = sm + 512;
    float* Hlo = Hhi + 128 * 36;
    float* Bh  = Hlo + 128 * 36;
    float* Bl  = Bh + 32 * 68;
    float* Cb  = Bl + 32 * 68;

    int tid = threadIdx.x;
    int w = tid >> 5;
    for (int i = tid; i < EB * HID; i += 128) sW1[i] = W1g[i];
    __syncthreads();

    int e = blockIdx.x * 128 + tid;
    bool valid = (e < E);

    // hidden activations -> tf32 hi/lo H rows
    {
        float hv[HID];
        if (valid) {
            float sv[EB];
            const float4* sp = (const float4*)(edge_sc + (size_t)e * EB);
#pragma unroll
            for (int i = 0; i < EB / 4; i++) {
                float4 v = sp[i];
                sv[i*4+0] = v.x; sv[i*4+1] = v.y; sv[i*4+2] = v.z; sv[i*4+3] = v.w;
            }
#pragma unroll
            for (int h = 0; h < HID; h++) {
                float t = 0.f;
#pragma unroll
                for (int i = 0; i < EB; i++) t += sv[i] * sW1[i * HID + h];
                t *= 0.25f;
                hv[h] = (t / (1.0f + __expf(-t))) * INV_SQRT32;
            }
        } else {
#pragma unroll
            for (int h = 0; h < HID; h++) hv[h] = 0.f;
        }
#pragma unroll
        for (int h = 0; h < HID; h++) {
            float hi = wmma::__float_to_tf32(hv[h]);
            Hhi[tid * 36 + h] = hi;
            Hlo[tid * 36 + h] = wmma::__float_to_tf32(hv[h] - hi);
        }
    }

    // per-edge epilogue operands
    float xs[M0], xvf[M1 * 3], pvv[M1], cr[M1 * 3];
    float sh0 = 0.f, shx = 0.f, shy = 0.f, shz = 0.f;
    int rcv = 0;
    if (valid) {
        int snd = eidx[e];
        rcv = eidx[E + e];
        const float4* xp = (const float4*)(node_ft + (size_t)snd * NODE_DIM);
#pragma unroll
        for (int i = 0; i < 4; i++) {
            float4 v = xp[i];
            xs[i*4+0] = v.x; xs[i*4+1] = v.y; xs[i*4+2] = v.z; xs[i*4+3] = v.w;
        }
#pragma unroll
        for (int i = 0; i < 6; i++) {
            float4 v = xp[4 + i];
            xvf[i*4+0] = v.x; xvf[i*4+1] = v.y; xvf[i*4+2] = v.z; xvf[i*4+3] = v.w;
        }
        float4 sh = ((const float4*)edge_sh)[e];
        sh0 = sh.x; shx = sh.y; shy = sh.z; shz = sh.w;
#pragma unroll
        for (int i = 0; i < M1; i++) {
            pvv[i] = (xvf[i*3+0]*shx + xvf[i*3+1]*shy + xvf[i*3+2]*shz) * INV_SQRT3;
            cr[i*3+0] = (xvf[i*3+1]*shz - xvf[i*3+2]*shy) * INV_SQRT2;
            cr[i*3+1] = (xvf[i*3+2]*shx - xvf[i*3+0]*shz) * INV_SQRT2;
            cr[i*3+2] = (xvf[i*3+0]*shy - xvf[i*3+1]*shx) * INV_SQRT2;
        }
    } else {
#pragma unroll
        for (int i = 0; i < M0; i++) xs[i] = 0.f;
#pragma unroll
        for (int i = 0; i < M1 * 3; i++) { xvf[i] = 0.f; cr[i] = 0.f; }
#pragma unroll
        for (int i = 0; i < M1; i++) pvv[i] = 0.f;
    }

    float sa[(PASS == 1) ? Q0 : O0];
    float va[(PASS == 1) ? Q1 * 3 : O1 * 3];
#pragma unroll
    for (int i = 0; i < ((PASS == 1) ? Q0 : O0); i++) sa[i] = 0.f;
#pragma unroll
    for (int i = 0; i < ((PASS == 1) ? Q1 * 3 : O1 * 3); i++) va[i] = 0.f;

    const float* Bgh = (PASS == 1) ? g_wk_hi : g_wv_hi;
    const float* Bgl = (PASS == 1) ? g_wk_lo : g_wv_lo;
    int kk = tid >> 2, part = tid & 3;

    for (int ch = 0; ch < NCH; ch++) {
        // stage B chunk [32][64] hi/lo
        {
            const float4* sh4 = (const float4*)(Bgh + kk * TP + ch * 64 + part * 16);
            const float4* sl4 = (const float4*)(Bgl + kk * TP + ch * 64 + part * 16);
            float4* dh4 = (float4*)(Bh + kk * 68 + part * 16);
            float4* dl4 = (float4*)(Bl + kk * 68 + part * 16);
#pragma unroll
            for (int q = 0; q < 4; q++) { dh4[q] = sh4[q]; dl4[q] = sl4[q]; }
        }
        __syncthreads();

        // GEMM: warp w owns m-tiles {2w, 2w+1}, 4 n-tiles of 16
        wmma::fragment<wmma::accumulator, 16, 16, 8, float> acc[2][4];
#pragma unroll
        for (int m = 0; m < 2; m++)
#pragma unroll
            for (int nt = 0; nt < 4; nt++) wmma::fill_fragment(acc[m][nt], 0.f);
#pragma unroll
        for (int k = 0; k < 4; k++) {
            wmma::fragment<wmma::matrix_a, 16, 16, 8, wmma::precision::tf32, wmma::row_major> ah[2], al[2];
#pragma unroll
            for (int m = 0; m < 2; m++) {
                wmma::load_matrix_sync(ah[m], Hhi + (w * 2 + m) * 16 * 36 + k * 8, 36);
                wmma::load_matrix_sync(al[m], Hlo + (w * 2 + m) * 16 * 36 + k * 8, 36);
            }
#pragma unroll
            for (int nt = 0; nt < 4; nt++) {
                wmma::fragment<wmma::matrix_b, 16, 16, 8, wmma::precision::tf32, wmma::row_major> bh, bl;
                wmma::load_matrix_sync(bh, Bh + k * 8 * 68 + nt * 16, 68);
                wmma::load_matrix_sync(bl, Bl + k * 8 * 68 + nt * 16, 68);
#pragma unroll
                for (int m = 0; m < 2; m++) {
                    wmma::mma_sync(acc[m][nt], ah[m], bh, acc[m][nt]);
                    wmma::mma_sync(acc[m][nt], ah[m], bl, acc[m][nt]);
                    wmma::mma_sync(acc[m][nt], al[m], bh, acc[m][nt]);
                }
            }
        }
#pragma unroll
        for (int m = 0; m < 2; m++)
#pragma unroll
            for (int nt = 0; nt < 4; nt++)
                wmma::store_matrix_sync(Cb + (w * 2 + m) * 16 * 68 + nt * 16,
                                        acc[m][nt], 68, wmma::mem_row_major);
        __syncthreads();

        // apply this thread's edge row
        if (valid) {
            const float4* rw = (const float4*)(Cb + tid * 68);
            int base = ch * 64;
#pragma unroll
            for (int j4 = 0; j4 < 16; j4++) {
                float4 v4 = rw[j4];
                apply1<PASS>(base + j4 * 4 + 0, v4.x, xs, pvv, xvf, cr, sh0, shx, shy, shz, sa, va);
                apply1<PASS>(base + j4 * 4 + 1, v4.y, xs, pvv, xvf, cr, sh0, shx, shy, shz, sa, va);
                apply1<PASS>(base + j4 * 4 + 2, v4.z, xs, pvv, xvf, cr, sh0, shx, shy, shz, sa, va);
                apply1<PASS>(base + j4 * 4 + 3, v4.w, xs, pvv, xvf, cr, sh0, shx, shy, shz, sa, va);
            }
        }
        __syncthreads();
    }

    if (valid) {
        if (PASS == 1) {
            const float* qts = g_qts + (size_t)rcv * Q0;
            const float* qtv = g_qtv + (size_t)rcv * 12;
            float dot = 0.f;
#pragma unroll
            for (int o = 0; o < Q0; o++) dot += qts[o] * sa[o];
#pragma unroll
            for (int j = 0; j < 12; j++) dot += qtv[j] * va[j];
            float ex = expf(dot);
            g_ex[e] = ex;
            atomicAdd(&g_z[rcv], ex);
        } else {
            float a = sqrtf(g_ex[e] / g_z[rcv]);
            float cs = a * INV_SQRT24, cv = a * INV_SQRT32;
            float* op = out + (size_t)rcv * OUT_DIM;
#pragma unroll
            for (int o = 0; o < O0; o++) atomicAdd(op + o, cs * sa[o]);
#pragma unroll
            for (int j = 0; j < O1 * 3; j++) atomicAdd(op + O0 + j, cv * va[j]);
        }
    }
}

// ---------------------------------------------------------------------------
extern "C" void kernel_launch(void* const* d_in, const int* in_sizes, int n_in,
                              void* d_out, int out_size)
{
    const float* node_ft = (const float*)d_in[0];
    const int* eidx      = (const int*)d_in[1];
    const float* edge_sh = (const float*)d_in[2];
    const float* edge_sc = (const float*)d_in[3];
    const float* wqs     = (const float*)d_in[4];
    const float* wqv     = (const float*)d_in[5];
    const float* fck_w1  = (const float*)d_in[6];
    const float* fck_w2  = (const float*)d_in[7];
    const float* fcv_w1  = (const float*)d_in[8];
    const float* fcv_w2  = (const float*)d_in[9];
    const float* wds     = (const float*)d_in[10];
    const float* wdv     = (const float*)d_in[11];
    float* out = (float*)d_out;

    int N = in_sizes[0] / NODE_DIM;
    int E = in_sizes[1] / 2;

    int smem = SMF * (int)sizeof(float);   // 91136 bytes
    cudaFuncSetAttribute(tf_pass<1>, cudaFuncAttributeMaxDynamicSharedMemorySize, smem);
    cudaFuncSetAttribute(tf_pass<2>, cudaFuncAttributeMaxDynamicSharedMemorySize, smem);

    q_kernel<<<(N + 127) / 128, 128>>>(node_ft, wqs, wqv, wds, wdv, out, N);
    prep_kernel<<<60, 256>>>(fck_w2, fcv_w2);

    int grid = (E + 127) / 128;
    tf_pass<1><<<grid, 128, smem>>>(node_ft, eidx, edge_sh, edge_sc, fck_w1, out, E);
    tf_pass<2><<<grid, 128, smem>>>(node_ft, eidx, edge_sh, edge_sc, fcv_w1, out, E);
}